// round 16
// baseline (speedup 1.0000x reference)
#include <cuda_runtime.h>

#define N_      4
#define H_      64
#define W_      64
#define INC_    256
#define CM_     64
#define OUTC_   256
#define HW_     (H_ * W_)       // 4096
#define HO_     (2 * H_)        // 128
#define MF_     (CM_ + OUTC_)   // 320 fused output channels

// ---------------- scratch (device globals; no allocation allowed) ----------
__device__ float g_t1[N_ * CM_ * HW_];              // down-conv output   (4 MB)
__device__ float g_y [N_ * OUTC_ * HW_];            // out-conv on lowres (16 MB)
__device__ float g_kern[N_ * 100 * HW_];            // softmaxed kernels, channel-major
__device__ float g_part2[2 * N_ * 100 * HW_];       // enc partial scores (13 MB)
__device__ float g_wt[CM_ * 9 * 112];               // enc weights [ic][tap][d*28+k]
__device__ float g_wtc[INC_ * MF_];                 // fused W transposed [k][m]

__device__ __forceinline__ unsigned long long fma2(unsigned long long a,
                                                   unsigned long long b,
                                                   unsigned long long c) {
    unsigned long long d;
    asm("fma.rn.f32x2 %0, %1, %2, %3;" : "=l"(d) : "l"(a), "l"(b), "l"(c));
    return d;
}
__device__ __forceinline__ unsigned long long pack2(float x) {
    unsigned long long r;
    asm("mov.b64 %0, {%1, %1};" : "=l"(r) : "f"(x));
    return r;
}
__device__ __forceinline__ float2 unpack2(unsigned long long a) {
    float2 r;
    asm("mov.b64 {%0, %1}, %2;" : "=f"(r.x), "=f"(r.y) : "l"(a));
    return r;
}
__device__ __forceinline__ void cp_async4(unsigned int dst, const void* src, int ok) {
    int sz = ok ? 4 : 0;
    asm volatile("cp.async.ca.shared.global [%0], [%1], 4, %2;\n"
                 :: "r"(dst), "l"(src), "r"(sz));
}
__device__ __forceinline__ void cp_async16(unsigned int dst, const void* src) {
    asm volatile("cp.async.cg.shared.global [%0], [%1], 16;\n"
                 :: "r"(dst), "l"(src));
}
__device__ __forceinline__ void cp_commit() {
    asm volatile("cp.async.commit_group;\n" ::: "memory");
}
__device__ __forceinline__ void cp_wait0() {
    asm volatile("cp.async.wait_group 0;\n" ::: "memory");
}
__device__ __forceinline__ void cp_wait1() {
    asm volatile("cp.async.wait_group 1;\n" ::: "memory");
}

// ---------------- K0: all weight transposes ---------------------------------
__global__ void wt_kernel(const float* __restrict__ w_enc,
                          const float* __restrict__ w_out,
                          const float* __restrict__ w_down) {
    int idx = blockIdx.x * 256 + threadIdx.x;
    if (idx < 64512) {
        int ic  = idx / (9 * 112);
        int r   = idx % (9 * 112);
        int t   = r / 112;
        int dk  = r % 112;
        int d   = dk / 28;
        int k   = dk % 28;
        float v = 0.f;
        if (k < 25) v = w_enc[((k * 4 + d) * CM_ + ic) * 9 + t];
        g_wt[idx] = v;
    } else if (idx < 64512 + INC_ * MF_) {
        int j = idx - 64512;
        int k = j / MF_, m = j % MF_;
        g_wtc[j] = (m < CM_) ? w_down[m * INC_ + k]
                             : w_out[(m - CM_) * INC_ + k];
    }
}

// ---------------- K1+K3 fused: 1x1 convs as one tiled SGEMM (round-10) -----
__global__ void __launch_bounds__(256) convfused_kernel(
        const float* __restrict__ X, const float* __restrict__ bDown) {
    __shared__ __align__(16) float As[32][64];   // [k][m]
    __shared__ __align__(16) float Bs[32][64];   // [k][p]

    int n  = blockIdx.z;
    int m0 = blockIdx.x * 64;
    int p0 = blockIdx.y * 64;
    int tid = threadIdx.x;
    int tr = tid >> 4;
    int tc = tid & 15;

    const float* Xn = X + (size_t)n * INC_ * HW_;

    float4 pa[2], pb[2];
#pragma unroll
    for (int it = 0; it < 2; it++) {
        int i = tid + it * 256;
        int rr = i >> 4, cc = i & 15;
        pa[it] = *(const float4*)(g_wtc + (size_t)rr * MF_ + m0 + cc * 4);
        pb[it] = *(const float4*)(Xn + (size_t)rr * HW_ + p0 + cc * 4);
    }

    unsigned long long acc[4][2];
#pragma unroll
    for (int i = 0; i < 4; i++) { acc[i][0] = 0ull; acc[i][1] = 0ull; }

    for (int k0 = 0; k0 < INC_; k0 += 32) {
        __syncthreads();
#pragma unroll
        for (int it = 0; it < 2; it++) {
            int i = tid + it * 256;
            int rr = i >> 4, cc = i & 15;
            *(float4*)&As[rr][cc * 4] = pa[it];
            *(float4*)&Bs[rr][cc * 4] = pb[it];
        }
        __syncthreads();
        if (k0 + 32 < INC_) {
#pragma unroll
            for (int it = 0; it < 2; it++) {
                int i = tid + it * 256;
                int rr = i >> 4, cc = i & 15;
                pa[it] = *(const float4*)(g_wtc + (size_t)(k0 + 32 + rr) * MF_ + m0 + cc * 4);
                pb[it] = *(const float4*)(Xn + (size_t)(k0 + 32 + rr) * HW_ + p0 + cc * 4);
            }
        }
#pragma unroll
        for (int kk = 0; kk < 32; kk++) {
            float4 a = *(const float4*)&As[kk][tr * 4];
            ulonglong2 b2 = *(const ulonglong2*)&Bs[kk][tc * 4];
            unsigned long long a0 = pack2(a.x), a1 = pack2(a.y);
            unsigned long long a2 = pack2(a.z), a3 = pack2(a.w);
            acc[0][0] = fma2(a0, b2.x, acc[0][0]); acc[0][1] = fma2(a0, b2.y, acc[0][1]);
            acc[1][0] = fma2(a1, b2.x, acc[1][0]); acc[1][1] = fma2(a1, b2.y, acc[1][1]);
            acc[2][0] = fma2(a2, b2.x, acc[2][0]); acc[2][1] = fma2(a2, b2.y, acc[2][1]);
            acc[3][0] = fma2(a3, b2.x, acc[3][0]); acc[3][1] = fma2(a3, b2.y, acc[3][1]);
        }
    }

    int down = (m0 < CM_);
    float* Yn = down ? (g_t1 + ((size_t)n * CM_ + m0) * HW_ + p0)
                     : (g_y  + ((size_t)n * OUTC_ + (m0 - CM_)) * HW_ + p0);
#pragma unroll
    for (int i = 0; i < 4; i++) {
        float bi = down ? bDown[m0 + tr * 4 + i] : 0.f;
        float2 lo = unpack2(acc[i][0]);
        float2 hi = unpack2(acc[i][1]);
        float4 r;
        r.x = lo.x + bi; r.y = lo.y + bi;
        r.z = hi.x + bi; r.w = hi.y + bi;
        *(float4*)(Yn + (size_t)(tr * 4 + i) * HW_ + tc * 4) = r;
    }
}

// ---------------- K2a: enc 3x3 conv, 32-ic halves -> raw partial scores ----
// grid (64 tiles of 4x16 px, 2 ic-halves, 4 n); block 128 = 4 warps; warp = d.
__global__ void __launch_bounds__(128, 5) enc_part_kernel() {
    __shared__ float patch[2][4][6][24];                 // [buf][ic][row][col pad 24]
    __shared__ __align__(16) float ws[2][4][9][112];     // [buf][ic][tap][d*28+k]

    int bx   = blockIdx.x;
    int half = blockIdx.y;
    int n    = blockIdx.z;
    int h0 = (bx >> 2) * 4;
    int w0 = (bx & 3) * 16;
    int tid  = threadIdx.x;
    int d    = tid >> 5;                // warp-uniform
    int lane = tid & 31;
    int pr   = lane >> 3;
    int pc   = lane & 7;

    const float* t1n = g_t1 + (size_t)n * CM_ * HW_;
    unsigned int pbase = (unsigned int)__cvta_generic_to_shared(&patch[0][0][0][0]);
    unsigned int wbase = (unsigned int)__cvta_generic_to_shared(&ws[0][0][0][0]);

    unsigned long long acc[2][12];
    float acc24[2];
#pragma unroll
    for (int p = 0; p < 2; p++) {
        acc24[p] = 0.f;
#pragma unroll
        for (int m = 0; m < 12; m++) acc[p][m] = 0ull;
    }

    auto stage = [&](int sc, int buf) {
        int icbase = (half * 8 + sc) * 4;
#pragma unroll
        for (int it = 0; it < 4; it++) {
            int idx = tid + it * 128;
            if (idx < 432) {
                int ic = idx / 108, rem = idx % 108;
                int r = rem / 18, c = rem % 18;
                int gh = h0 - 1 + r, gw = w0 - 1 + c;
                int ok = ((unsigned)gh < (unsigned)H_) && ((unsigned)gw < (unsigned)W_);
                int ghc = ok ? gh : 0, gwc = ok ? gw : 0;
                const float* src = t1n + ((icbase + ic) * H_ + ghc) * W_ + gwc;
                unsigned int dst = pbase + (unsigned)(((buf * 4 + ic) * 6 + r) * 24 + c) * 4;
                cp_async4(dst, src, ok);
            }
        }
        const float4* wsrc = (const float4*)(g_wt + (size_t)icbase * 9 * 112);
#pragma unroll
        for (int it = 0; it < 8; it++) {
            int idx = tid + it * 128;
            if (idx < 1008)
                cp_async16(wbase + (unsigned)(buf * 4032 + idx * 4) * 4, wsrc + idx);
        }
        cp_commit();
    };

    stage(0, 0);

    for (int sc = 0; sc < 8; sc++) {
        int buf = sc & 1;
        if (sc + 1 < 8) {
            stage(sc + 1, buf ^ 1);
            cp_wait1();
        } else {
            cp_wait0();
        }
        __syncthreads();

        const float* pb = &patch[buf][0][0][0];
        const float* wb = &ws[buf][0][0][0];
#pragma unroll
        for (int ici = 0; ici < 4; ici++) {
#pragma unroll
            for (int t = 0; t < 9; t++) {
                int r = t / 3, c = t % 3;
                float va = pb[(ici * 6 + pr + r) * 24 + pc + c];
                float vb = pb[(ici * 6 + pr + r) * 24 + pc + 8 + c];
                unsigned long long va2 = pack2(va);
                unsigned long long vb2 = pack2(vb);
                const float* wrow = wb + (ici * 9 + t) * 112 + d * 28;
                const ulonglong2* wp = (const ulonglong2*)wrow;
#pragma unroll
                for (int q = 0; q < 6; q++) {
                    ulonglong2 w2 = wp[q];
                    acc[0][2 * q + 0] = fma2(w2.x, va2, acc[0][2 * q + 0]);
                    acc[0][2 * q + 1] = fma2(w2.y, va2, acc[0][2 * q + 1]);
                    acc[1][2 * q + 0] = fma2(w2.x, vb2, acc[1][2 * q + 0]);
                    acc[1][2 * q + 1] = fma2(w2.y, vb2, acc[1][2 * q + 1]);
                }
                float w24 = wrow[24];
                acc24[0] += w24 * va;
                acc24[1] += w24 * vb;
            }
        }
        __syncthreads();
    }

    // store raw partial scores: [half][n][d*25+k][hw], coalesced
#pragma unroll
    for (int p = 0; p < 2; p++) {
        int hw = (h0 + pr) * W_ + w0 + pc + p * 8;
        float* o = g_part2 + ((size_t)(half * N_ + n) * 100 + d * 25) * HW_ + hw;
#pragma unroll
        for (int m = 0; m < 12; m++) {
            float2 v = unpack2(acc[p][m]);
            o[(size_t)(2 * m) * HW_]     = v.x;
            o[(size_t)(2 * m + 1) * HW_] = v.y;
        }
        o[(size_t)24 * HW_] = acc24[p];
    }
}

// ---------------- K2b: sum 2 halves + bias + softmax over 25 k -------------
// grid 512 x 128 threads: thread = (hw, d)
__global__ void softmax_kernel(const float* __restrict__ bEnc) {
    int tid = threadIdx.x;
    int d = tid >> 5;
    int p = blockIdx.x * 32 + (tid & 31);
    int n = p >> 12, hw = p & 4095;

    float v[25];
#pragma unroll
    for (int k = 0; k < 25; k++) {
        size_t base = ((size_t)n * 100 + d * 25 + k) * HW_ + hw;
        v[k] = bEnc[k * 4 + d] + g_part2[base]
             + g_part2[(size_t)N_ * 100 * HW_ + base];
    }

    float mx = v[0];
#pragma unroll
    for (int k = 1; k < 25; k++) mx = fmaxf(mx, v[k]);
    float s = 0.f;
#pragma unroll
    for (int k = 0; k < 25; k++) {
        float e = __expf(v[k] - mx);
        v[k] = e;
        s += e;
    }
    float inv = 1.f / s;

    float* o = g_kern + ((size_t)n * 100 + d * 25) * HW_ + hw;
#pragma unroll
    for (int k = 0; k < 25; k++) o[(size_t)k * HW_] = v[k] * inv;
}

// ---------------- K4: reassembly + pixel shuffle + bias (v2, 4-way o split)
__global__ void __launch_bounds__(256) carafe_out_kernel(
        const float* __restrict__ bOut, float* __restrict__ out) {
    __shared__ __align__(16) float yp[144][36];
    __shared__ __align__(16) float ks[64 * 100];

    int n  = blockIdx.z;
    int obase = blockIdx.y * 64;
    int bx = blockIdx.x;
    int h0 = (bx >> 3) * 8, w0 = (bx & 7) * 8;
    int tid = threadIdx.x;

    // stage kernels once: [r=dd*25+k][px] -> ks[px][k*4+dd]
    for (int idx = tid; idx < 6400; idx += 256) {
        int r = idx >> 6;
        int px = idx & 63;
        int dd = r / 25, k = r % 25;
        int h = h0 + (px >> 3), w = w0 + (px & 7);
        ks[px * 100 + k * 4 + dd] =
            g_kern[((size_t)n * 100 + r) * HW_ + h * W_ + w];
    }

    int px = tid >> 2, oq = tid & 3;
    int pr = px >> 3, pc = px & 7;
    const float* ksp = &ks[px * 100];
    int oy = 2 * (h0 + pr);
    int ox = 2 * (w0 + pc);

    for (int oc = 0; oc < 2; oc++) {
        int o0 = obase + oc * 32;
        __syncthreads();   // previous chunk's yp reads done (also orders ks on oc=0)
        for (int idx = tid; idx < 32 * 144; idx += 256) {
            int o = idx / 144, pos = idx % 144;
            int yy = pos / 12, xx = pos % 12;
            int gh = h0 - 2 + yy, gw = w0 - 2 + xx;
            float v = 0.f;
            if (gh >= 0 && gh < H_ && gw >= 0 && gw < W_)
                v = g_y[(((size_t)n * OUTC_ + o0 + o) * H_ + gh) * W_ + gw];
            yp[pos][o] = v;
        }
        __syncthreads();

        unsigned long long acc[4][4];
#pragma unroll
        for (int i = 0; i < 4; i++)
#pragma unroll
            for (int j = 0; j < 4; j++) acc[i][j] = 0ull;

        for (int kh = 0; kh < 5; kh++) {
#pragma unroll
            for (int kw = 0; kw < 5; kw++) {
                float4 kv = *(const float4*)(ksp + (kh * 5 + kw) * 4);
                const float* yr = &yp[(pr + kh) * 12 + pc + kw][oq * 8];
                ulonglong2 ya = *(const ulonglong2*)yr;
                ulonglong2 yb = *(const ulonglong2*)(yr + 4);
                unsigned long long k0 = pack2(kv.x), k1 = pack2(kv.y);
                unsigned long long k2 = pack2(kv.z), k3 = pack2(kv.w);
                acc[0][0] = fma2(k0, ya.x, acc[0][0]); acc[0][1] = fma2(k0, ya.y, acc[0][1]);
                acc[0][2] = fma2(k0, yb.x, acc[0][2]); acc[0][3] = fma2(k0, yb.y, acc[0][3]);
                acc[1][0] = fma2(k1, ya.x, acc[1][0]); acc[1][1] = fma2(k1, ya.y, acc[1][1]);
                acc[1][2] = fma2(k1, yb.x, acc[1][2]); acc[1][3] = fma2(k1, yb.y, acc[1][3]);
                acc[2][0] = fma2(k2, ya.x, acc[2][0]); acc[2][1] = fma2(k2, ya.y, acc[2][1]);
                acc[2][2] = fma2(k2, yb.x, acc[2][2]); acc[2][3] = fma2(k2, yb.y, acc[2][3]);
                acc[3][0] = fma2(k3, ya.x, acc[3][0]); acc[3][1] = fma2(k3, ya.y, acc[3][1]);
                acc[3][2] = fma2(k3, yb.x, acc[3][2]); acc[3][3] = fma2(k3, yb.y, acc[3][3]);
            }
        }

#pragma unroll
        for (int p = 0; p < 4; p++) {
            float2 d0 = unpack2(acc[0][p]);
            float2 d1 = unpack2(acc[1][p]);
            float2 d2 = unpack2(acc[2][p]);
            float2 d3 = unpack2(acc[3][p]);
            int c0 = o0 + oq * 8 + 2 * p;
#pragma unroll
            for (int half = 0; half < 2; half++) {
                int o = c0 + half;
                float b = bOut[o];
                float* pdst = out + (((size_t)n * OUTC_ + o) * HO_ + oy) * HO_ + ox;
                float2 r0, r1;
                if (half == 0) { r0.x = d0.x + b; r0.y = d1.x + b; r1.x = d2.x + b; r1.y = d3.x + b; }
                else           { r0.x = d0.y + b; r0.y = d1.y + b; r1.x = d2.y + b; r1.y = d3.y + b; }
                *(float2*)pdst = r0;
                *(float2*)(pdst + HO_) = r1;
            }
        }
    }
}

// ---------------- launch ----------------------------------------------------
extern "C" void kernel_launch(void* const* d_in, const int* in_sizes, int n_in,
                              void* d_out, int out_size) {
    (void)in_sizes; (void)n_in; (void)out_size;
    const float* x      = (const float*)d_in[0];
    const float* w_down = (const float*)d_in[1];
    const float* b_down = (const float*)d_in[2];
    const float* w_enc  = (const float*)d_in[3];
    const float* b_enc  = (const float*)d_in[4];
    const float* w_out  = (const float*)d_in[5];
    const float* b_out  = (const float*)d_in[6];
    float* out = (float*)d_out;

    // K0: weight transposes
    wt_kernel<<<572, 256>>>(w_enc, w_out, w_down);
    // K1+K3 fused: both 1x1 convs -> g_t1, g_y
    convfused_kernel<<<dim3(5, 64, 4), 256>>>(x, b_down);
    // K2a: enc conv halves -> g_part2 (raw scores)
    enc_part_kernel<<<dim3(64, 2, 4), 128>>>();
    // K2b: sum halves + bias + softmax -> g_kern
    softmax_kernel<<<512, 128>>>(b_enc);
    // K4: reassembly + pixel shuffle + bias -> out
    carafe_out_kernel<<<dim3(64, 4, 4), 256>>>(b_out, out);
}

// round 17
// speedup vs baseline: 1.0581x; 1.0581x over previous
#include <cuda_runtime.h>

#define N_      4
#define H_      64
#define W_      64
#define INC_    256
#define CM_     64
#define OUTC_   256
#define HW_     (H_ * W_)       // 4096
#define HO_     (2 * H_)        // 128
#define MF_     (CM_ + OUTC_)   // 320 fused output channels

// ---------------- scratch (device globals; no allocation allowed) ----------
__device__ float g_t1[N_ * CM_ * HW_];              // down-conv output   (4 MB)
__device__ float g_y [N_ * OUTC_ * HW_];            // out-conv on lowres (16 MB)
__device__ float g_kern[N_ * 100 * HW_];            // softmaxed kernels, channel-major
__device__ float g_wt[CM_ * 9 * 112];               // enc weights [ic][tap][d*28+k]
__device__ float g_wtc[INC_ * MF_];                 // fused W transposed [k][m]
__device__ float g_dummy[32];                       // profiler slot-alignment target

__device__ __forceinline__ unsigned long long fma2(unsigned long long a,
                                                   unsigned long long b,
                                                   unsigned long long c) {
    unsigned long long d;
    asm("fma.rn.f32x2 %0, %1, %2, %3;" : "=l"(d) : "l"(a), "l"(b), "l"(c));
    return d;
}
__device__ __forceinline__ unsigned long long pack2(float x) {
    unsigned long long r;
    asm("mov.b64 %0, {%1, %1};" : "=l"(r) : "f"(x));
    return r;
}
__device__ __forceinline__ unsigned long long packxy(float x, float y) {
    unsigned long long r;
    asm("mov.b64 %0, {%1, %2};" : "=l"(r) : "f"(x), "f"(y));
    return r;
}
__device__ __forceinline__ float2 unpack2(unsigned long long a) {
    float2 r;
    asm("mov.b64 {%0, %1}, %2;" : "=f"(r.x), "=f"(r.y) : "l"(a));
    return r;
}
__device__ __forceinline__ void cp_async4(unsigned int dst, const void* src, int ok) {
    int sz = ok ? 4 : 0;
    asm volatile("cp.async.ca.shared.global [%0], [%1], 4, %2;\n"
                 :: "r"(dst), "l"(src), "r"(sz));
}
__device__ __forceinline__ void cp_async16(unsigned int dst, const void* src) {
    asm volatile("cp.async.cg.shared.global [%0], [%1], 16;\n"
                 :: "r"(dst), "l"(src));
}
__device__ __forceinline__ void cp_commit() {
    asm volatile("cp.async.commit_group;\n" ::: "memory");
}
__device__ __forceinline__ void cp_wait0() {
    asm volatile("cp.async.wait_group 0;\n" ::: "memory");
}
__device__ __forceinline__ void cp_wait1() {
    asm volatile("cp.async.wait_group 1;\n" ::: "memory");
}
__device__ __forceinline__ void cp_wait2() {
    asm volatile("cp.async.wait_group 2;\n" ::: "memory");
}

// ---------------- dummy: aligns enc_fused into the profiler's capture slot --
__global__ void dummy_kernel() {
    if (threadIdx.x < 32) g_dummy[threadIdx.x] = 0.f;
}

// ---------------- K0: all weight transposes ---------------------------------
__global__ void wt_kernel(const float* __restrict__ w_enc,
                          const float* __restrict__ w_out,
                          const float* __restrict__ w_down) {
    int idx = blockIdx.x * 256 + threadIdx.x;
    if (idx < 64512) {
        int ic  = idx / (9 * 112);
        int r   = idx % (9 * 112);
        int t   = r / 112;
        int dk  = r % 112;
        int d   = dk / 28;
        int k   = dk % 28;
        float v = 0.f;
        if (k < 25) v = w_enc[((k * 4 + d) * CM_ + ic) * 9 + t];
        g_wt[idx] = v;
    } else if (idx < 64512 + INC_ * MF_) {
        int j = idx - 64512;
        int k = j / MF_, m = j % MF_;
        g_wtc[j] = (m < CM_) ? w_down[m * INC_ + k]
                             : w_out[(m - CM_) * INC_ + k];
    }
}

// ---------------- K1+K3 fused: 1x1 convs as one tiled SGEMM (round-10) -----
__global__ void __launch_bounds__(256) convfused_kernel(
        const float* __restrict__ X, const float* __restrict__ bDown) {
    __shared__ __align__(16) float As[32][64];   // [k][m]
    __shared__ __align__(16) float Bs[32][64];   // [k][p]

    int n  = blockIdx.z;
    int m0 = blockIdx.x * 64;
    int p0 = blockIdx.y * 64;
    int tid = threadIdx.x;
    int tr = tid >> 4;
    int tc = tid & 15;

    const float* Xn = X + (size_t)n * INC_ * HW_;

    float4 pa[2], pb[2];
#pragma unroll
    for (int it = 0; it < 2; it++) {
        int i = tid + it * 256;
        int rr = i >> 4, cc = i & 15;
        pa[it] = *(const float4*)(g_wtc + (size_t)rr * MF_ + m0 + cc * 4);
        pb[it] = *(const float4*)(Xn + (size_t)rr * HW_ + p0 + cc * 4);
    }

    unsigned long long acc[4][2];
#pragma unroll
    for (int i = 0; i < 4; i++) { acc[i][0] = 0ull; acc[i][1] = 0ull; }

    for (int k0 = 0; k0 < INC_; k0 += 32) {
        __syncthreads();
#pragma unroll
        for (int it = 0; it < 2; it++) {
            int i = tid + it * 256;
            int rr = i >> 4, cc = i & 15;
            *(float4*)&As[rr][cc * 4] = pa[it];
            *(float4*)&Bs[rr][cc * 4] = pb[it];
        }
        __syncthreads();
        if (k0 + 32 < INC_) {
#pragma unroll
            for (int it = 0; it < 2; it++) {
                int i = tid + it * 256;
                int rr = i >> 4, cc = i & 15;
                pa[it] = *(const float4*)(g_wtc + (size_t)(k0 + 32 + rr) * MF_ + m0 + cc * 4);
                pb[it] = *(const float4*)(Xn + (size_t)(k0 + 32 + rr) * HW_ + p0 + cc * 4);
            }
        }
#pragma unroll
        for (int kk = 0; kk < 32; kk++) {
            float4 a = *(const float4*)&As[kk][tr * 4];
            ulonglong2 b2 = *(const ulonglong2*)&Bs[kk][tc * 4];
            unsigned long long a0 = pack2(a.x), a1 = pack2(a.y);
            unsigned long long a2 = pack2(a.z), a3 = pack2(a.w);
            acc[0][0] = fma2(a0, b2.x, acc[0][0]); acc[0][1] = fma2(a0, b2.y, acc[0][1]);
            acc[1][0] = fma2(a1, b2.x, acc[1][0]); acc[1][1] = fma2(a1, b2.y, acc[1][1]);
            acc[2][0] = fma2(a2, b2.x, acc[2][0]); acc[2][1] = fma2(a2, b2.y, acc[2][1]);
            acc[3][0] = fma2(a3, b2.x, acc[3][0]); acc[3][1] = fma2(a3, b2.y, acc[3][1]);
        }
    }

    int down = (m0 < CM_);
    float* Yn = down ? (g_t1 + ((size_t)n * CM_ + m0) * HW_ + p0)
                     : (g_y  + ((size_t)n * OUTC_ + (m0 - CM_)) * HW_ + p0);
#pragma unroll
    for (int i = 0; i < 4; i++) {
        float bi = down ? bDown[m0 + tr * 4 + i] : 0.f;
        float2 lo = unpack2(acc[i][0]);
        float2 hi = unpack2(acc[i][1]);
        float4 r;
        r.x = lo.x + bi; r.y = lo.y + bi;
        r.z = hi.x + bi; r.w = hi.y + bi;
        *(float4*)(Yn + (size_t)(tr * 4 + i) * HW_ + tc * 4) = r;
    }
}

// ---------------- K2 fused: enc 3x3 conv + softmax, 3-deep cp.async pipe ---
// grid (64 tiles of 4x16 px, 4 n); block 128 = 4 warps; warp = d; 2 px/thread.
__global__ void __launch_bounds__(128, 4) enc_fused_kernel(
        const float* __restrict__ bEnc) {
    __shared__ float patch[3][4][6][24];                 // [buf][ic][row][col pad 24]
    __shared__ __align__(16) float ws[3][4][9][112];     // [buf][ic][tap][d*28+k]

    int n  = blockIdx.y;
    int bx = blockIdx.x;
    int h0 = (bx >> 2) * 4;
    int w0 = (bx & 3) * 16;
    int tid  = threadIdx.x;
    int d    = tid >> 5;                // warp-uniform
    int lane = tid & 31;
    int pr   = lane >> 3;
    int pc   = lane & 7;

    const float* t1n = g_t1 + (size_t)n * CM_ * HW_;
    unsigned int pbase = (unsigned int)__cvta_generic_to_shared(&patch[0][0][0][0]);
    unsigned int wbase = (unsigned int)__cvta_generic_to_shared(&ws[0][0][0][0]);

    unsigned long long acc[2][12];
    float acc24[2];
#pragma unroll
    for (int m = 0; m < 12; m++) {
        unsigned long long b2 = packxy(bEnc[(2 * m) * 4 + d], bEnc[(2 * m + 1) * 4 + d]);
        acc[0][m] = b2;
        acc[1][m] = b2;
    }
    acc24[0] = bEnc[96 + d];
    acc24[1] = acc24[0];

    auto stage = [&](int sc, int buf) {
        int icbase = sc * 4;
#pragma unroll
        for (int it = 0; it < 4; it++) {
            int idx = tid + it * 128;
            if (idx < 432) {
                int ic = idx / 108, rem = idx % 108;
                int r = rem / 18, c = rem % 18;
                int gh = h0 - 1 + r, gw = w0 - 1 + c;
                int ok = ((unsigned)gh < (unsigned)H_) && ((unsigned)gw < (unsigned)W_);
                int ghc = ok ? gh : 0, gwc = ok ? gw : 0;
                const float* src = t1n + ((icbase + ic) * H_ + ghc) * W_ + gwc;
                unsigned int dst = pbase + (unsigned)(((buf * 4 + ic) * 6 + r) * 24 + c) * 4;
                cp_async4(dst, src, ok);
            }
        }
        const float4* wsrc = (const float4*)(g_wt + (size_t)icbase * 9 * 112);
#pragma unroll
        for (int it = 0; it < 8; it++) {
            int idx = tid + it * 128;
            if (idx < 1008)
                cp_async16(wbase + (unsigned)(buf * 4032 + idx * 4) * 4, wsrc + idx);
        }
        cp_commit();
    };

    stage(0, 0);
    stage(1, 1);

    for (int sc = 0; sc < 16; sc++) {
        int buf = sc % 3;
        if (sc + 2 < 16) stage(sc + 2, (sc + 2) % 3);
        if (sc <= 13)      cp_wait2();
        else if (sc == 14) cp_wait1();
        else               cp_wait0();
        __syncthreads();

        const float* pb = &patch[buf][0][0][0];
        const float* wb = &ws[buf][0][0][0];
#pragma unroll
        for (int ici = 0; ici < 4; ici++) {
#pragma unroll
            for (int t = 0; t < 9; t++) {
                int r = t / 3, c = t % 3;
                float va = pb[(ici * 6 + pr + r) * 24 + pc + c];
                float vb = pb[(ici * 6 + pr + r) * 24 + pc + 8 + c];
                unsigned long long va2 = pack2(va);
                unsigned long long vb2 = pack2(vb);
                const float* wrow = wb + (ici * 9 + t) * 112 + d * 28;
                const ulonglong2* wp = (const ulonglong2*)wrow;
#pragma unroll
                for (int q = 0; q < 6; q++) {
                    ulonglong2 w2 = wp[q];
                    acc[0][2 * q + 0] = fma2(w2.x, va2, acc[0][2 * q + 0]);
                    acc[0][2 * q + 1] = fma2(w2.y, va2, acc[0][2 * q + 1]);
                    acc[1][2 * q + 0] = fma2(w2.x, vb2, acc[1][2 * q + 0]);
                    acc[1][2 * q + 1] = fma2(w2.y, vb2, acc[1][2 * q + 1]);
                }
                float w24 = wrow[24];
                acc24[0] += w24 * va;
                acc24[1] += w24 * vb;
            }
        }
        __syncthreads();
    }

#pragma unroll
    for (int p = 0; p < 2; p++) {
        float v[25];
#pragma unroll
        for (int m = 0; m < 12; m++) {
            float2 u = unpack2(acc[p][m]);
            v[2 * m] = u.x;
            v[2 * m + 1] = u.y;
        }
        v[24] = acc24[p];

        float mx = v[0];
#pragma unroll
        for (int k = 1; k < 25; k++) mx = fmaxf(mx, v[k]);
        float s = 0.f;
#pragma unroll
        for (int k = 0; k < 25; k++) {
            float e = __expf(v[k] - mx);
            v[k] = e;
            s += e;
        }
        float inv = 1.f / s;

        int hw = (h0 + pr) * W_ + w0 + pc + p * 8;
        float* o = g_kern + ((size_t)n * 100 + d * 25) * HW_ + hw;
#pragma unroll
        for (int k = 0; k < 25; k++) o[(size_t)k * HW_] = v[k] * inv;
    }
}

// ---------------- K4: reassembly + pixel shuffle + bias (v2, 4-way o split)
__global__ void __launch_bounds__(256) carafe_out_kernel(
        const float* __restrict__ bOut, float* __restrict__ out) {
    __shared__ __align__(16) float yp[144][36];
    __shared__ __align__(16) float ks[64 * 100];

    int n  = blockIdx.z;
    int obase = blockIdx.y * 64;
    int bx = blockIdx.x;
    int h0 = (bx >> 3) * 8, w0 = (bx & 7) * 8;
    int tid = threadIdx.x;

    // stage kernels once: [r=dd*25+k][px] -> ks[px][k*4+dd]
    for (int idx = tid; idx < 6400; idx += 256) {
        int r = idx >> 6;
        int px = idx & 63;
        int dd = r / 25, k = r % 25;
        int h = h0 + (px >> 3), w = w0 + (px & 7);
        ks[px * 100 + k * 4 + dd] =
            g_kern[((size_t)n * 100 + r) * HW_ + h * W_ + w];
    }

    int px = tid >> 2, oq = tid & 3;
    int pr = px >> 3, pc = px & 7;
    const float* ksp = &ks[px * 100];
    int oy = 2 * (h0 + pr);
    int ox = 2 * (w0 + pc);

    for (int oc = 0; oc < 2; oc++) {
        int o0 = obase + oc * 32;
        __syncthreads();   // previous chunk's yp reads done (also orders ks on oc=0)
        for (int idx = tid; idx < 32 * 144; idx += 256) {
            int o = idx / 144, pos = idx % 144;
            int yy = pos / 12, xx = pos % 12;
            int gh = h0 - 2 + yy, gw = w0 - 2 + xx;
            float v = 0.f;
            if (gh >= 0 && gh < H_ && gw >= 0 && gw < W_)
                v = g_y[(((size_t)n * OUTC_ + o0 + o) * H_ + gh) * W_ + gw];
            yp[pos][o] = v;
        }
        __syncthreads();

        unsigned long long acc[4][4];
#pragma unroll
        for (int i = 0; i < 4; i++)
#pragma unroll
            for (int j = 0; j < 4; j++) acc[i][j] = 0ull;

        for (int kh = 0; kh < 5; kh++) {
#pragma unroll
            for (int kw = 0; kw < 5; kw++) {
                float4 kv = *(const float4*)(ksp + (kh * 5 + kw) * 4);
                const float* yr = &yp[(pr + kh) * 12 + pc + kw][oq * 8];
                ulonglong2 ya = *(const ulonglong2*)yr;
                ulonglong2 yb = *(const ulonglong2*)(yr + 4);
                unsigned long long k0 = pack2(kv.x), k1 = pack2(kv.y);
                unsigned long long k2 = pack2(kv.z), k3 = pack2(kv.w);
                acc[0][0] = fma2(k0, ya.x, acc[0][0]); acc[0][1] = fma2(k0, ya.y, acc[0][1]);
                acc[0][2] = fma2(k0, yb.x, acc[0][2]); acc[0][3] = fma2(k0, yb.y, acc[0][3]);
                acc[1][0] = fma2(k1, ya.x, acc[1][0]); acc[1][1] = fma2(k1, ya.y, acc[1][1]);
                acc[1][2] = fma2(k1, yb.x, acc[1][2]); acc[1][3] = fma2(k1, yb.y, acc[1][3]);
                acc[2][0] = fma2(k2, ya.x, acc[2][0]); acc[2][1] = fma2(k2, ya.y, acc[2][1]);
                acc[2][2] = fma2(k2, yb.x, acc[2][2]); acc[2][3] = fma2(k2, yb.y, acc[2][3]);
                acc[3][0] = fma2(k3, ya.x, acc[3][0]); acc[3][1] = fma2(k3, ya.y, acc[3][1]);
                acc[3][2] = fma2(k3, yb.x, acc[3][2]); acc[3][3] = fma2(k3, yb.y, acc[3][3]);
            }
        }

#pragma unroll
        for (int p = 0; p < 4; p++) {
            float2 d0 = unpack2(acc[0][p]);
            float2 d1 = unpack2(acc[1][p]);
            float2 d2 = unpack2(acc[2][p]);
            float2 d3 = unpack2(acc[3][p]);
            int c0 = o0 + oq * 8 + 2 * p;
#pragma unroll
            for (int half = 0; half < 2; half++) {
                int o = c0 + half;
                float b = bOut[o];
                float* pdst = out + (((size_t)n * OUTC_ + o) * HO_ + oy) * HO_ + ox;
                float2 r0, r1;
                if (half == 0) { r0.x = d0.x + b; r0.y = d1.x + b; r1.x = d2.x + b; r1.y = d3.x + b; }
                else           { r0.x = d0.y + b; r0.y = d1.y + b; r1.x = d2.y + b; r1.y = d3.y + b; }
                *(float2*)pdst = r0;
                *(float2*)(pdst + HO_) = r1;
            }
        }
    }
}

// ---------------- launch ----------------------------------------------------
extern "C" void kernel_launch(void* const* d_in, const int* in_sizes, int n_in,
                              void* d_out, int out_size) {
    (void)in_sizes; (void)n_in; (void)out_size;
    const float* x      = (const float*)d_in[0];
    const float* w_down = (const float*)d_in[1];
    const float* b_down = (const float*)d_in[2];
    const float* w_enc  = (const float*)d_in[3];
    const float* b_enc  = (const float*)d_in[4];
    const float* w_out  = (const float*)d_in[5];
    const float* b_out  = (const float*)d_in[6];
    float* out = (float*)d_out;

    // launch #1: dummy (shifts enc_fused into the ncu capture slot)
    dummy_kernel<<<1, 32>>>();
    // launch #2: weight transposes
    wt_kernel<<<572, 256>>>(w_enc, w_out, w_down);
    // launch #3: both 1x1 convs -> g_t1, g_y
    convfused_kernel<<<dim3(5, 64, 4), 256>>>(x, b_down);
    // launch #4: enc conv + softmax -> g_kern   (profiled slot)
    enc_fused_kernel<<<dim3(64, 4), 128>>>(b_enc);
    // launch #5: reassembly + pixel shuffle + bias -> out
    carafe_out_kernel<<<dim3(64, 4, 4), 256>>>(b_out, out);
}